// round 4
// baseline (speedup 1.0000x reference)
#include <cuda_runtime.h>
#include <cuda_bf16.h>

// MatchSegmentation, single fused kernel.
//   ce[k,g] = -( C_k + sum_{n: gi[g,n]=1} d[k,n] ) / N,  d = log(s+e)-log(1-s+e)
//   argmin_g ce == argmax_g D[k,g]  (positive scale ok -> log2, drop constants)
//
// Inputs identified by size signature; seg vs gt disambiguated on-device by
// bit pattern (gt int words are 0/1). Output = float32 indices.
//
// Single kernel: per-block probe -> tile loop (mask build, log2, transposed
// smem sweep) -> per-block partials to g_part -> last block reduces + argmax.

#define EPS 1e-6f
#define T_MAX 512
#define KREF 21
#define SD_FLOATS (KREF * (T_MAX + 20))   // 11172 floats = 44688 B
#define MAXGRID 304
#define MAXPAIR 2048
#define GMAX 32

__device__ float g_part[MAXPAIR * MAXGRID];
__device__ unsigned g_cnt = 0;

__global__ __launch_bounds__(512) void ms_fused_kernel(
    const void* __restrict__ Av, const void* __restrict__ Bv,
    const int* __restrict__ gpn, float* __restrict__ out,
    int out_size, int N, int K, int P, int T, int TPAD, int grid, int nprobe)
{
    __shared__ float sd[SD_FLOATS];            // transposed: sd[k*TPAD + t]
    __shared__ unsigned smask[T_MAX];
    __shared__ int s_tmp[2];
    __shared__ int s_cfg[2];                   // [0]=asel, [1]=G
    __shared__ float s_D[KREF * GMAX];
    __shared__ unsigned s_done;

    const int j = threadIdx.x;

    // ---- per-block parallel probe: which big input is segmentation? ----
    if (j < 64) {
        int i = j & 31;
        int idx = (i < nprobe) ? i : 0;
        unsigned w = (j < 32) ? ((const unsigned*)Av)[idx]
                              : ((const unsigned*)Bv)[idx];
        unsigned bal = __ballot_sync(0xffffffffu, w > 1u);
        if ((j & 31) == 0) s_tmp[j >> 5] = __popc(bal);
    }
    __syncthreads();
    if (j == 0) {
        s_cfg[0] = (s_tmp[0] >= s_tmp[1]) ? 1 : 0;   // 1 -> A is seg
        int G = gpn ? *gpn : 20;
        if (G < 1 || G > 1000000) G = 20;
        if (G > GMAX) G = GMAX;
        if (G > P) G = P;
        if (G < 1) G = 1;
        s_cfg[1] = G;
    }
    __syncthreads();

    const int asel = s_cfg[0];
    const float* __restrict__ seg = asel ? (const float*)Av : (const float*)Bv;
    const int*   __restrict__ gt  = asel ? (const int*)Bv  : (const int*)Av;
    const int G = s_cfg[1];
    int NPAIR = K * G;
    if (NPAIR > MAXPAIR) NPAIR = MAXPAIR;

    // ---- pair ownership (up to 4 pairs per thread) ----
    int k0 = -1, k1 = -1, k2 = -1, k3 = -1;
    unsigned b0 = 0, b1 = 0, b2 = 0, b3 = 0;
    if (j < NPAIR)        { k0 = j / G;          b0 = 1u << (j % G); }
    if (j + 512 < NPAIR)  { k1 = (j + 512) / G;  b1 = 1u << ((j + 512) % G); }
    if (j + 1024 < NPAIR) { k2 = (j + 1024) / G; b2 = 1u << ((j + 1024) % G); }
    if (j + 1536 < NPAIR) { k3 = (j + 1536) / G; b3 = 1u << ((j + 1536) % G); }
    float acc0 = 0.0f, acc1 = 0.0f, acc2 = 0.0f, acc3 = 0.0f;

    const int ntiles = (N + T - 1) / T;

    for (int tile = blockIdx.x; tile < ntiles; tile += gridDim.x) {
        const int base = tile * T;
        const int nt = min(T, N - base);

        // ---- Phase 1a: per-pixel GT bit masks ----
        if (((nt & 3) == 0) && ((base & 3) == 0) && ((N & 3) == 0)) {
            int nq = nt >> 2;
            for (int q = j; q < nq; q += 512) {
                unsigned m0 = 0, m1 = 0, m2 = 0, m3 = 0;
                const int* gp = gt + base + 4 * q;
                for (int g = 0; g < G; g++) {
                    int4 v = *(const int4*)(gp + (size_t)g * N);
                    unsigned bit = 1u << g;
                    if (v.x) m0 |= bit;
                    if (v.y) m1 |= bit;
                    if (v.z) m2 |= bit;
                    if (v.w) m3 |= bit;
                }
                smask[4 * q + 0] = m0;
                smask[4 * q + 1] = m1;
                smask[4 * q + 2] = m2;
                smask[4 * q + 3] = m3;
            }
        } else {
            for (int t = j; t < nt; t += 512) {
                unsigned m = 0;
                for (int g = 0; g < G; g++)
                    if (gt[(size_t)g * N + base + t]) m |= 1u << g;
                smask[t] = m;
            }
        }

        // ---- Phase 1b: d = log2(s+e)-log2(1-s+e), TRANSPOSED to sd[k][t] ----
        const int nelem = nt * K;
        const size_t off = (size_t)base * (size_t)K;
        if (((off & 3) == 0) && ((nelem & 3) == 0)) {
            const float4* sv = (const float4*)(seg + off);
            int n4 = nelem >> 2;
            for (int q = j; q < n4; q += 512) {
                float4 s = sv[q];
                int e = 4 * q;
                float d0 = __log2f(s.x + EPS) - __log2f(1.0f - s.x + EPS);
                float d1 = __log2f(s.y + EPS) - __log2f(1.0f - s.y + EPS);
                float d2 = __log2f(s.z + EPS) - __log2f(1.0f - s.z + EPS);
                float d3 = __log2f(s.w + EPS) - __log2f(1.0f - s.w + EPS);
                int t0 = e / K,       kk0 = e - t0 * K;
                int t1 = (e+1) / K,   kk1 = (e+1) - t1 * K;
                int t2 = (e+2) / K,   kk2 = (e+2) - t2 * K;
                int t3 = (e+3) / K,   kk3 = (e+3) - t3 * K;
                sd[kk0 * TPAD + t0] = d0;
                sd[kk1 * TPAD + t1] = d1;
                sd[kk2 * TPAD + t2] = d2;
                sd[kk3 * TPAD + t3] = d3;
            }
        } else {
            for (int e = j; e < nelem; e += 512) {
                float s = seg[off + e];
                int t = e / K, kk = e - t * K;
                sd[kk * TPAD + t] = __log2f(s + EPS) - __log2f(1.0f - s + EPS);
            }
        }
        __syncthreads();

        // ---- Phase 2: vectorized sweep (2x LDS.128 per 4 pixels) ----
        const int nt4 = nt & ~3;
        if (k0 >= 0) {
            const float* sdk = sd + k0 * TPAD;
            float a = 0.0f;
            for (int t = 0; t < nt4; t += 4) {
                uint4 m = *(const uint4*)(smask + t);
                float4 dv = *(const float4*)(sdk + t);
                if (m.x & b0) a += dv.x;
                if (m.y & b0) a += dv.y;
                if (m.z & b0) a += dv.z;
                if (m.w & b0) a += dv.w;
            }
            for (int t = nt4; t < nt; t++)
                if (smask[t] & b0) a += sdk[t];
            acc0 += a;
        }
        if (k1 >= 0) {
            const float* sdk = sd + k1 * TPAD;
            float a = 0.0f;
            for (int t = 0; t < nt4; t += 4) {
                uint4 m = *(const uint4*)(smask + t);
                float4 dv = *(const float4*)(sdk + t);
                if (m.x & b1) a += dv.x;
                if (m.y & b1) a += dv.y;
                if (m.z & b1) a += dv.z;
                if (m.w & b1) a += dv.w;
            }
            for (int t = nt4; t < nt; t++)
                if (smask[t] & b1) a += sdk[t];
            acc1 += a;
        }
        if (k2 >= 0) {
            const float* sdk = sd + k2 * TPAD;
            float a = 0.0f;
            for (int t = 0; t < nt4; t += 4) {
                uint4 m = *(const uint4*)(smask + t);
                float4 dv = *(const float4*)(sdk + t);
                if (m.x & b2) a += dv.x;
                if (m.y & b2) a += dv.y;
                if (m.z & b2) a += dv.z;
                if (m.w & b2) a += dv.w;
            }
            for (int t = nt4; t < nt; t++)
                if (smask[t] & b2) a += sdk[t];
            acc2 += a;
        }
        if (k3 >= 0) {
            const float* sdk = sd + k3 * TPAD;
            float a = 0.0f;
            for (int t = 0; t < nt4; t += 4) {
                uint4 m = *(const uint4*)(smask + t);
                float4 dv = *(const float4*)(sdk + t);
                if (m.x & b3) a += dv.x;
                if (m.y & b3) a += dv.y;
                if (m.z & b3) a += dv.z;
                if (m.w & b3) a += dv.w;
            }
            for (int t = nt4; t < nt; t++)
                if (smask[t] & b3) a += sdk[t];
            acc3 += a;
        }
        __syncthreads();
    }

    // ---- write per-block partials (no zeroing needed: pure writes) ----
    const int blk = blockIdx.x;
    if (k0 >= 0) g_part[j * MAXGRID + blk] = acc0;
    if (k1 >= 0) g_part[(j + 512) * MAXGRID + blk] = acc1;
    if (k2 >= 0) g_part[(j + 1024) * MAXGRID + blk] = acc2;
    if (k3 >= 0) g_part[(j + 1536) * MAXGRID + blk] = acc3;

    // ---- last-block reduction + argmax ----
    __threadfence();
    if (j == 0) s_done = atomicAdd(&g_cnt, 1u);
    __syncthreads();
    if (s_done == (unsigned)(grid - 1)) {
        for (int p = j; p < NPAIR; p += 512) {
            float sum = 0.0f;
            const float* row = &g_part[p * MAXGRID];
            for (int b = 0; b < grid; b++)
                sum += __ldcg(row + b);        // L2 read: bypass stale L1
            int kk = p / G, gg = p - kk * G;
            if (kk < KREF) s_D[kk * GMAX + gg] = sum;
        }
        __syncthreads();
        for (int k = j; k < out_size; k += 512) {
            if (k < K && k < KREF) {
                float best = s_D[k * GMAX];
                int bi = 0;
                for (int g = 1; g < G; g++) {
                    float v = s_D[k * GMAX + g];
                    if (v > best) { best = v; bi = g; }  // first-max tie rule
                }
                out[k] = (float)bi;
            } else {
                out[k] = 0.0f;
            }
        }
        if (j == 0) g_cnt = 0;                 // reset for next graph replay
    }
}

extern "C" void kernel_launch(void* const* d_in, const int* in_sizes, int n_in,
                              void* d_out, int out_size)
{
    // ---- identify inputs by size signature (ordering-invariant) ----
    int imax = 0;
    for (int i = 1; i < n_in; i++)
        if (in_sizes[i] > in_sizes[imax]) imax = i;
    int jmax = -1;
    for (int i = 0; i < n_in; i++)
        if (i != imax && in_sizes[i] == in_sizes[imax]) { jmax = i; break; }
    if (jmax < 0) {
        imax = 0;
        jmax = (n_in > 2) ? 2 : (n_in > 1 ? 1 : 0);
    }

    int N = 1;
    int gpn_idx = -1;
    for (int i = 0; i < n_in; i++) {
        if (i == imax || i == jmax) continue;
        if (in_sizes[i] > N) N = in_sizes[i];
        if (in_sizes[i] == 1) gpn_idx = i;
    }
    if (N < 1) N = 1;
    long long M = in_sizes[imax];
    int K = (int)(M / N);
    if (K < 1) K = 1;
    if (K > KREF) K = KREF;     // fixed-shape problem; smem sized for K<=21

    const int* gpn = (gpn_idx >= 0) ? (const int*)d_in[gpn_idx] : nullptr;

    // tile size: K*(T+20) floats must fit SD_FLOATS, T multiple of 4
    int T = T_MAX;
    if (K * (T + 20) > SD_FLOATS) {
        T = ((SD_FLOATS / K) - 20) & ~3;
        if (T < 4) T = 4;
    }
    int TPAD = T + 20;

    int ntiles = (N + T - 1) / T;
    int grid = ntiles < 296 ? ntiles : 296;
    if (grid > MAXGRID) grid = MAXGRID;
    if (grid < 1) grid = 1;

    int nprobe = (int)(M < 32 ? M : 32);
    if (nprobe < 1) nprobe = 1;

    ms_fused_kernel<<<grid, 512>>>(d_in[imax], d_in[jmax], gpn,
                                   (float*)d_out, out_size,
                                   N, K, (K < KREF ? K : KREF) /*P clamp*/,
                                   T, TPAD, grid, nprobe);
}